// round 15
// baseline (speedup 1.0000x reference)
#include <cuda_runtime.h>
#include <cuda_fp16.h>
#include <cstddef>
#include <cstdint>

#define HH 320
#define WW 320
#define CC 64
#define BB 2
#define HW (HH*WW)              // 102400
#define CHW ((size_t)CC*HW)     // 6553600
#define TENSOR_ELEMS (BB*CHW)   // 13107200
#define CPHW ((size_t)32*HW)    // pair-planes per batch image

// Scratch (static device arrays; no allocation allowed)
__device__ uint32_t g_Mth[2*CC*32];          // fp16x2 Mt pairs: [dir][b][ap]
__device__ uint32_t g_bufh[2][BB*CPHW];      // attention buffers, fp16 pair-packed
__device__ uint32_t g_th[2][BB*CPHW];        // conv1 outputs, fp16 pair-packed
__device__ uint32_t g_uh[BB*CPHW];           // fp16 pair-packed u (written by kattn)
__device__ uint32_t g_dh[BB*CPHW];           // fp16 pair-packed d
// fp16 conv weights: [chunk][tap9][o64][kp8] half2 words
__device__ uint32_t g_wh1a[8*9*64*8];
__device__ uint32_t g_wh2a[8*9*64*8];
__device__ uint32_t g_wh1b[4*9*64*8];
__device__ uint32_t g_wh2b[4*9*64*8];

__device__ __forceinline__ void mma_f16(float4& d,
        uint32_t a0, uint32_t a1, uint32_t a2, uint32_t a3,
        uint32_t b0, uint32_t b1) {
    asm("mma.sync.aligned.m16n8k16.row.col.f32.f16.f16.f32 "
        "{%0,%1,%2,%3}, {%4,%5,%6,%7}, {%8,%9}, {%0,%1,%2,%3};"
        : "+f"(d.x), "+f"(d.y), "+f"(d.z), "+f"(d.w)
        : "r"(a0), "r"(a1), "r"(a2), "r"(a3), "r"(b0), "r"(b1));
}
__device__ __forceinline__ uint32_t prmt(uint32_t lo, uint32_t hi, uint32_t sel) {
    uint32_t r; asm("prmt.b32 %0, %1, %2, %3;" : "=r"(r) : "r"(lo), "r"(hi), "r"(sel));
    return r;
}
__device__ __forceinline__ void cp16(uint32_t saddr, const void* gaddr, uint32_t sz) {
    asm volatile("cp.async.cg.shared.global [%0], [%1], 16, %2;"
                 :: "r"(saddr), "l"(gaddr), "r"(sz));
}
__device__ __forceinline__ uint32_t h2u(__half2 h) { return *(uint32_t*)&h; }

// ---------------------------------------------------------------------------
// prep: fp16 conv weights (kp perm + sigma rows)
// ---------------------------------------------------------------------------
__device__ __forceinline__ void prepwh_one(const float* __restrict__ W,
                                           uint32_t* __restrict__ dst,
                                           int cin, int i) {
    int w      = i & 7;
    int o_st   = (i >> 3) & 63;
    int t      = (i >> 9) % 9;
    int chunk  = i / (9*64*8);
    int kpc = (w >> 1) + (w & 1)*4;
    int c0  = chunk*16 + 2*kpc;
    int r   = o_st & 15, tb = o_st & 48;
    int oc  = tb + (r & 7)*2 + (r >> 3);
    float w0 = W[((size_t)oc*cin + c0)*9 + t];
    float w1 = W[((size_t)oc*cin + c0 + 1)*9 + t];
    dst[i] = h2u(__floats2half2_rn(w0, w1));
}

#define WHA (8*9*64*8)   // 36864
#define WHB (4*9*64*8)   // 18432

__global__ void kprepwAll(const float* __restrict__ W1a, const float* __restrict__ W2a,
                          const float* __restrict__ W1b, const float* __restrict__ W2b) {
    int total = 2*WHA + 2*WHB;
    for (int i = blockIdx.x*256 + threadIdx.x; i < total; i += gridDim.x*256) {
        if (i < WHA)               prepwh_one(W1a, g_wh1a, 128, i);
        else if (i < 2*WHA)        prepwh_one(W2a, g_wh2a, 128, i - WHA);
        else if (i < 2*WHA + WHB)  prepwh_one(W1b, g_wh1b, 64,  i - 2*WHA);
        else                       prepwh_one(W2b, g_wh2b, 64,  i - 2*WHA - WHB);
    }
}

// ---------------------------------------------------------------------------
// Kernel 1: Mth[dir][b][ap] = half2( log2e*Mt[b][2ap], log2e*Mt[b][2ap+1] )
// ---------------------------------------------------------------------------
__global__ void kcomputeM2(const float* __restrict__ Wu1, const float* __restrict__ Wd2,
                           const float* __restrict__ Wd1, const float* __restrict__ Wu2) {
    __shared__ float sq[64*64];
    __shared__ float sk[64*64];
    int dir = blockIdx.x;
    const float* Wq = dir ? Wd1 : Wu1;
    const float* Wk = dir ? Wu2 : Wd2;
    int t = threadIdx.x;
    for (int i = t; i < 4096; i += 256) { sq[i] = Wq[i]; sk[i] = Wk[i]; }
    __syncthreads();
    const float LOG2E = 1.4426950408889634f;
    for (int i = t; i < 2048; i += 256) {
        int b  = i & 63;
        int ap = i >> 6;
        float s0 = 0.f, s1 = 0.f;
        #pragma unroll 16
        for (int c = 0; c < 64; c++) {
            s0 += sq[c*64 + 2*ap]     * sk[c*64 + b];
            s1 += sq[c*64 + 2*ap + 1] * sk[c*64 + b];
        }
        g_Mth[dir*2048 + b*32 + ap] = h2u(__floats2half2_rn(s0*LOG2E, s1*LOG2E));
    }
}

// ---------------------------------------------------------------------------
// Kernel 2: fp16 attention, register softmax (no max pass) — unchanged (R14).
// ---------------------------------------------------------------------------
#define SP  328
#define SPH 172
#define SRP 40
#define ATTN_SMEM ((2*32*SP + 32*SPH + 32*SRP + 64*40 + 256)*4)

__global__ __launch_bounds__(512)
void kattn(const float* __restrict__ u, const float* __restrict__ d) {
    extern __shared__ uint32_t sm[];
    uint32_t* sup = sm;
    uint32_t* sdp = sm + 32*SP;
    uint32_t* sPh = sm + 2*32*SP;
    uint32_t* sRp = sPh + 32*SPH;
    float*    sO  = (float*)(sRp + 32*SRP);
    float*    sPsum = sO + 64*40;

    int tid  = threadIdx.x;
    int lane = tid & 31, warp = tid >> 5;    // 16 warps
    int gid  = lane >> 2, tid4 = lane & 3;
    int b = blockIdx.x / HH, h = blockIdx.x % HH;
    const float* ubase = u + (size_t)b*CHW + (size_t)h*WW;
    const float* dbase = d + (size_t)b*CHW + (size_t)h*WW;

    for (int i = tid; i < 32*80; i += 512) {
        int cp = i / 80, vq = (i % 80)*4;
        float4 ue = *(const float4*)(ubase + (size_t)(2*cp)*HW + vq);
        float4 uo = *(const float4*)(ubase + (size_t)(2*cp+1)*HW + vq);
        float4 de = *(const float4*)(dbase + (size_t)(2*cp)*HW + vq);
        float4 do_ = *(const float4*)(dbase + (size_t)(2*cp+1)*HW + vq);
        uint4 wu, wd;
        wu.x = h2u(__floats2half2_rn(ue.x, uo.x));
        wu.y = h2u(__floats2half2_rn(ue.y, uo.y));
        wu.z = h2u(__floats2half2_rn(ue.z, uo.z));
        wu.w = h2u(__floats2half2_rn(ue.w, uo.w));
        wd.x = h2u(__floats2half2_rn(de.x, do_.x));
        wd.y = h2u(__floats2half2_rn(de.y, do_.y));
        wd.z = h2u(__floats2half2_rn(de.z, do_.z));
        wd.w = h2u(__floats2half2_rn(de.w, do_.w));
        *(uint4*)&sup[cp*SP + vq] = wu;
        *(uint4*)&sdp[cp*SP + vq] = wd;
        size_t go = (size_t)b*CPHW + (size_t)cp*HW + (size_t)h*WW + vq;
        *(uint4*)&g_uh[go] = wu;
        *(uint4*)&g_dh[go] = wd;
    }

    for (int dir = 0; dir < 2; dir++) {
        const uint32_t* sQ = dir ? sdp : sup;
        const uint32_t* sV = dir ? sup : sdp;
        uint32_t* outgh = g_bufh[dir] + (size_t)b*CPHW + (size_t)h*WW;

        const uint32_t* Mth = g_Mth + dir*2048;
        int bg = warp & 3, rq = warp >> 2;
        int r = bg*16 + gid;
        uint32_t am[4][4];
        #pragma unroll
        for (int kk = 0; kk < 4; kk++) {
            am[kk][0] = Mth[r*32 + kk*8 + tid4];
            am[kk][1] = Mth[(r+8)*32 + kk*8 + tid4];
            am[kk][2] = Mth[r*32 + kk*8 + tid4 + 4];
            am[kk][3] = Mth[(r+8)*32 + kk*8 + tid4 + 4];
        }

        for (int q0 = 0; q0 < WW; q0 += 32) {
            __syncthreads();

            // ---- R[b][q]: 16b x 8q per warp, K=64 ----
            {
                float4 rc = make_float4(0.f,0.f,0.f,0.f);
                int qc = q0 + rq*8 + gid;
                #pragma unroll
                for (int kk = 0; kk < 4; kk++) {
                    uint32_t b0 = sQ[(kk*8 + tid4)*SP + qc];
                    uint32_t b1 = sQ[(kk*8 + tid4 + 4)*SP + qc];
                    mma_f16(rc, am[kk][0], am[kk][1], am[kk][2], am[kk][3], b0, b1);
                }
                __half* rh = (__half*)sRp;
                int bp  = bg*8 + (gid >> 1);
                int par = gid & 1;
                int qq  = rq*8 + 2*tid4;
                rh[(bp*SRP + qq)*2 + par]         = __float2half_rn(rc.x);
                rh[(bp*SRP + qq + 1)*2 + par]     = __float2half_rn(rc.y);
                rh[((bp+4)*SRP + qq)*2 + par]     = __float2half_rn(rc.z);
                rh[((bp+4)*SRP + qq + 1)*2 + par] = __float2half_rn(rc.w);
            }
            __syncthreads();

            // ---- S[q][v] in registers + register softmax (no max pass) ----
            {
                int qg = warp >> 3, vg = warp & 7;
                float4 sc[5];
                #pragma unroll
                for (int nt = 0; nt < 5; nt++) sc[nt] = make_float4(0.f,0.f,0.f,0.f);
                #pragma unroll
                for (int kk = 0; kk < 4; kk++) {
                    uint32_t a0 = sRp[(kk*8 + tid4)*SRP + qg*16 + gid];
                    uint32_t a1 = sRp[(kk*8 + tid4)*SRP + qg*16 + gid + 8];
                    uint32_t a2 = sRp[(kk*8 + tid4 + 4)*SRP + qg*16 + gid];
                    uint32_t a3 = sRp[(kk*8 + tid4 + 4)*SRP + qg*16 + gid + 8];
                    #pragma unroll
                    for (int nt = 0; nt < 5; nt++) {
                        int vv = vg*40 + nt*8 + gid;
                        uint32_t b0 = sV[(kk*8 + tid4)*SP + vv];
                        uint32_t b1 = sV[(kk*8 + tid4 + 4)*SP + vv];
                        mma_f16(sc[nt], a0, a1, a2, a3, b0, b1);
                    }
                }
                int row0 = qg*16 + gid;
                float s0 = 0.f, s1 = 0.f;
                #pragma unroll
                for (int nt = 0; nt < 5; nt++) {
                    sc[nt].x = exp2f(sc[nt].x);
                    sc[nt].y = exp2f(sc[nt].y);
                    sc[nt].z = exp2f(sc[nt].z);
                    sc[nt].w = exp2f(sc[nt].w);
                    s0 += sc[nt].x + sc[nt].y;
                    s1 += sc[nt].z + sc[nt].w;
                }
                s0 += __shfl_xor_sync(~0u, s0, 1);
                s0 += __shfl_xor_sync(~0u, s0, 2);
                s1 += __shfl_xor_sync(~0u, s1, 1);
                s1 += __shfl_xor_sync(~0u, s1, 2);
                if (tid4 == 0) {
                    sPsum[row0*8 + vg]     = s0;
                    sPsum[(row0+8)*8 + vg] = s1;
                }
                __syncthreads();
                float4 ga = *(const float4*)&sPsum[row0*8];
                float4 gb = *(const float4*)&sPsum[row0*8 + 4];
                float inv0 = 1.f / (ga.x + ga.y + ga.z + ga.w + gb.x + gb.y + gb.z + gb.w);
                ga = *(const float4*)&sPsum[(row0+8)*8];
                gb = *(const float4*)&sPsum[(row0+8)*8 + 4];
                float inv1 = 1.f / (ga.x + ga.y + ga.z + ga.w + gb.x + gb.y + gb.z + gb.w);
                #pragma unroll
                for (int nt = 0; nt < 5; nt++) {
                    int vp = vg*20 + nt*4 + tid4;
                    sPh[row0*SPH + vp]     = h2u(__floats2half2_rn(sc[nt].x*inv0, sc[nt].y*inv0));
                    sPh[(row0+8)*SPH + vp] = h2u(__floats2half2_rn(sc[nt].z*inv1, sc[nt].w*inv1));
                }
            }
            __syncthreads();

            // ---- attend: warp = cg(4) x aqg(2) x kh(2); rows = adjacent ch pair ----
            {
                int cg = warp & 3, aqg = (warp >> 2) & 1, kh = warp >> 3;
                int gam = cg*8 + gid;
                int c0  = 2*gam;
                float4 oc[2];
                oc[0] = make_float4(0.f,0.f,0.f,0.f);
                oc[1] = make_float4(0.f,0.f,0.f,0.f);
                #pragma unroll 2
                for (int kk = 0; kk < 10; kk++) {
                    int kb = kh*160 + kk*16;
                    uint2 w0 = *(const uint2*)&sV[gam*SP + kb + 2*tid4];
                    uint2 w1 = *(const uint2*)&sV[gam*SP + kb + 2*tid4 + 8];
                    uint32_t a0 = prmt(w0.x, w0.y, 0x5410u);
                    uint32_t a1 = prmt(w0.x, w0.y, 0x7632u);
                    uint32_t a2 = prmt(w1.x, w1.y, 0x5410u);
                    uint32_t a3 = prmt(w1.x, w1.y, 0x7632u);
                    int vp = (kb >> 1) + tid4;
                    #pragma unroll
                    for (int nt = 0; nt < 2; nt++) {
                        int q = aqg*16 + nt*8 + gid;
                        uint32_t b0 = sPh[q*SPH + vp];
                        uint32_t b1 = sPh[q*SPH + vp + 4];
                        mma_f16(oc[nt], a0, a1, a2, a3, b0, b1);
                    }
                }
                if (kh == 0) {
                    #pragma unroll
                    for (int nt = 0; nt < 2; nt++) {
                        int q = aqg*16 + nt*8 + 2*tid4;
                        *(float2*)&sO[c0*40 + q]     = make_float2(oc[nt].x, oc[nt].y);
                        *(float2*)&sO[(c0+1)*40 + q] = make_float2(oc[nt].z, oc[nt].w);
                    }
                }
                __syncthreads();
                if (kh == 1) {
                    #pragma unroll
                    for (int nt = 0; nt < 2; nt++) {
                        int q = aqg*16 + nt*8 + 2*tid4;
                        float2 r0 = *(const float2*)&sO[c0*40 + q];
                        float2 r1 = *(const float2*)&sO[(c0+1)*40 + q];
                        uint2 wv;
                        wv.x = h2u(__floats2half2_rn(oc[nt].x + r0.x, oc[nt].z + r1.x));
                        wv.y = h2u(__floats2half2_rn(oc[nt].y + r0.y, oc[nt].w + r1.y));
                        *(uint2*)(outgh + (size_t)gam*HW + q0 + q) = wv;
                    }
                }
            }
        }
        __syncthreads();
    }
}

// ---------------------------------------------------------------------------
// Kernel 3: fp16 conv with pixel-major input smem (B fragments = one LDS.64).
// cp.async stages raw pair-plane strip (stride 728); per-chunk smem repack
// into [pix][8] with plane order (0,4,1,5,2,6,3,7).
// ---------------------------------------------------------------------------
#define SIN2 5760                       // input region words: 720 pix * 8
#define SWH  (9*64*8)                   // 4608
#define STH2 (SIN2 + SWH)               // 10368
#define STRIPW 5824                     // strip: 8 planes * 728
#define CONVH_SMEM ((2*STH2 + STRIPW)*4)   // 106240 bytes

template<int CIN, bool FUSE>
__global__ __launch_bounds__(512, 1)
void kconvH(const uint32_t* __restrict__ in1u, const uint32_t* __restrict__ in1d,
            const uint32_t* __restrict__ in2u, const uint32_t* __restrict__ in2d,
            const uint32_t* __restrict__ wpu,  const uint32_t* __restrict__ wpd,
            void* __restrict__ outu, void* __restrict__ outd) {
    extern __shared__ uint32_t csm[];
    uint32_t* strip = csm + 2*STH2;

    int tid  = threadIdx.x;
    int lane = tid & 31, warp = tid >> 5;
    int x0 = blockIdx.x * 64;
    int y0 = blockIdx.y * 8;
    int z  = blockIdx.z;
    int b  = z & 1, st = z >> 1;

    const uint32_t* in1 = (st ? in1d : in1u) + (size_t)b*CPHW;
    const uint32_t* in2 = (CIN == 128) ? ((st ? in2d : in2u) + (size_t)b*CPHW) : nullptr;
    const uint32_t* wp  = st ? wpd  : wpu;
    void* outv          = st ? outd : outu;

    int warp_o = warp & 1;
    int warp_y = warp >> 1;         // 0..7
    int lq = lane >> 2;
    int lr = lane & 3;

    uint32_t s_base     = (uint32_t)__cvta_generic_to_shared(csm);
    uint32_t strip_base = s_base + 2*STH2*4;
    const int NCH = CIN/16;

    // ---- chunk-invariant staging decomposition (into strip) ----
    bool has3 = tid < 416;          // 1440 = 2*512 + 416
    int      pc_c[3];
    uint32_t pc_soff[3];
    int      pc_roff[3];
    uint32_t pc_ok[3];
    #pragma unroll
    for (int j = 0; j < 3; j++) {
        int i = tid + j*512;
        if (i < 1440) {
            int c   = i / 180;
            int rem = i % 180;
            int rr  = rem / 18;
            int qd  = rem % 18;
            int gy = y0 + rr - 1;
            int gx = x0 - 4 + qd*4;
            uint32_t ok = (gy >= 0 && gy < HH && gx >= 0 && gx < WW) ? 16u : 0u;
            pc_c[j]    = c;
            pc_soff[j] = strip_base + (uint32_t)(c*728 + rr*72 + qd*4)*4;
            pc_roff[j] = ok ? gy*WW + gx : 0;
            pc_ok[j]   = ok;
        } else {
            pc_c[j] = 0; pc_soff[j] = strip_base; pc_roff[j] = 0; pc_ok[j] = 0;
        }
    }

    auto stage = [&](int cb, int bufi) {
        // input -> strip
        #pragma unroll
        for (int j = 0; j < 3; j++) {
            if (j == 2 && !has3) break;
            int cpg = cb*8 + pc_c[j];
            const uint32_t* plane = (CIN == 128 && cpg >= 32)
                                  ? in2 + (size_t)(cpg - 32)*HW
                                  : in1 + (size_t)cpg*HW;
            cp16(pc_soff[j], plane + pc_roff[j], pc_ok[j]);
        }
        // weights -> buffer directly
        uint32_t wb = s_base + (bufi*STH2 + SIN2)*4;
        const uint32_t* wsrc = wp + cb*SWH;
        #pragma unroll
        for (int j = 0; j < 3; j++) {
            int i = tid + j*512;
            if (i < SWH/4)
                cp16(wb + i*16, wsrc + i*4, 16);
        }
    };

    // repack strip -> pixel-major input region of buffer bufi
    auto repack = [&](int bufi) {
        uint32_t* dst = csm + bufi*STH2;
        #pragma unroll
        for (int j = 0; j < 3; j++) {
            int idx = tid + j*512;
            if (idx < 1440) {
                int pix = idx >> 1, hh = idx & 1;
                uint32_t r0 = strip[(2*hh + 0)*728 + pix];
                uint32_t r1 = strip[(2*hh + 4)*728 + pix];
                uint32_t r2 = strip[(2*hh + 1)*728 + pix];
                uint32_t r3 = strip[(2*hh + 5)*728 + pix];
                *(uint4*)&dst[pix*8 + hh*4] = make_uint4(r0, r1, r2, r3);
            }
        }
    };

    float4 acc[2][8];
    #pragma unroll
    for (int mt = 0; mt < 2; mt++)
        #pragma unroll
        for (int nt = 0; nt < 8; nt++) acc[mt][nt] = make_float4(0.f,0.f,0.f,0.f);

    stage(0, 0);
    asm volatile("cp.async.commit_group;" ::: "memory");
    asm volatile("cp.async.wait_group 0;" ::: "memory");
    __syncthreads();
    repack(0);
    __syncthreads();

    for (int cb = 0; cb < NCH; cb++) {
        if (cb + 1 < NCH) {
            stage(cb + 1, (cb + 1) & 1);
            asm volatile("cp.async.commit_group;" ::: "memory");
        }

        const uint32_t* sin_ = csm + (cb & 1)*STH2;
        const uint32_t* sw_  = sin_ + SIN2;

        #pragma unroll
        for (int t = 0; t < 9; t++) {
            int ky = t/3, kx = t - ky*3;
            int row = warp_y + ky;
            int pbase = (row*72 + kx + 3 + lq)*8 + 2*lr;
            uint2 ae0 = *(const uint2*)&sw_[(t*64 + warp_o*32 + lq)*8 + 2*lr];
            uint2 ao0 = *(const uint2*)&sw_[(t*64 + warp_o*32 + lq + 8)*8 + 2*lr];
            uint2 ae1 = *(const uint2*)&sw_[(t*64 + warp_o*32 + 16 + lq)*8 + 2*lr];
            uint2 ao1 = *(const uint2*)&sw_[(t*64 + warp_o*32 + 16 + lq + 8)*8 + 2*lr];
            #pragma unroll
            for (int nt = 0; nt < 8; nt++) {
                uint2 bb = *(const uint2*)&sin_[pbase + 64*nt];
                mma_f16(acc[0][nt], ae0.x, ao0.x, ae0.y, ao0.y, bb.x, bb.y);
                mma_f16(acc[1][nt], ae1.x, ao1.x, ae1.y, ao1.y, bb.x, bb.y);
            }
        }

        if (cb + 1 < NCH) {
            asm volatile("cp.async.wait_group 0;" ::: "memory");
            __syncthreads();             // compute(cb) done + strip arrived
            repack((cb + 1) & 1);
            __syncthreads();
        }
    }

    // ---- writeback: rows = adjacent channel pair (sigma) ----
    int y = y0 + warp_y;
    #pragma unroll
    for (int mt = 0; mt < 2; mt++) {
        int tb  = warp_o*32 + mt*16;
        int ch0 = tb + 2*lq;
        int cp  = (tb >> 1) + lq;
        #pragma unroll
        for (int nt = 0; nt < 8; nt++) {
            int x = x0 + nt*8 + 2*lr;
            float4 v = acc[mt][nt];
            if (FUSE) {
                uint32_t* outp = (uint32_t*)outv;
                uint2 wv;
                wv.x = h2u(__floats2half2_rn(fmaxf(v.x, 0.f), fmaxf(v.z, 0.f)));
                wv.y = h2u(__floats2half2_rn(fmaxf(v.y, 0.f), fmaxf(v.w, 0.f)));
                *(uint2*)(outp + (size_t)b*CPHW + (size_t)cp*HW + (size_t)y*WW + x) = wv;
            } else {
                float* outp = (float*)outv;
                size_t off = (size_t)b*CHW + (size_t)ch0*HW + (size_t)y*WW + x;
                *(float2*)(outp + off)      = make_float2(v.x, v.y);
                *(float2*)(outp + off + HW) = make_float2(v.z, v.w);
            }
        }
    }
}

// ---------------------------------------------------------------------------
extern "C" void kernel_launch(void* const* d_in, const int* in_sizes, int n_in,
                              void* d_out, int out_size) {
    const float* u   = (const float*)d_in[0];
    const float* d   = (const float*)d_in[1];
    const float* Wu1 = (const float*)d_in[2];
    const float* Wu2 = (const float*)d_in[3];
    const float* Wd1 = (const float*)d_in[4];
    const float* Wd2 = (const float*)d_in[5];
    const float* W1a = (const float*)d_in[6];
    const float* W1b = (const float*)d_in[7];
    const float* W2a = (const float*)d_in[8];
    const float* W2b = (const float*)d_in[9];
    float* out = (float*)d_out;

    cudaFuncSetAttribute(kattn, cudaFuncAttributeMaxDynamicSharedMemorySize, ATTN_SMEM);
    cudaFuncSetAttribute(kconvH<128, true>,  cudaFuncAttributeMaxDynamicSharedMemorySize, CONVH_SMEM);
    cudaFuncSetAttribute(kconvH<64, false>,  cudaFuncAttributeMaxDynamicSharedMemorySize, CONVH_SMEM);

    uint32_t *pbuf0, *pbuf1, *pt0, *pt1, *puh, *pdh;
    uint32_t *pw1a, *pw2a, *pw1b, *pw2b;
    cudaGetSymbolAddress((void**)&pbuf0, g_bufh);  pbuf1 = pbuf0 + BB*CPHW;
    cudaGetSymbolAddress((void**)&pt0,   g_th);    pt1   = pt0   + BB*CPHW;
    cudaGetSymbolAddress((void**)&puh,   g_uh);
    cudaGetSymbolAddress((void**)&pdh,   g_dh);
    cudaGetSymbolAddress((void**)&pw1a,  g_wh1a);
    cudaGetSymbolAddress((void**)&pw2a,  g_wh2a);
    cudaGetSymbolAddress((void**)&pw1b,  g_wh1b);
    cudaGetSymbolAddress((void**)&pw2b,  g_wh2b);

    kprepwAll<<<432, 256>>>(W1a, W2a, W1b, W2b);
    kcomputeM2<<<2, 256>>>(Wu1, Wd2, Wd1, Wu2);

    kattn<<<BB*HH, 512, ATTN_SMEM>>>(u, d);

    dim3 grid(WW/64, HH/8, 4);
    kconvH<128, true><<<grid, 512, CONVH_SMEM>>>(puh, pdh, pbuf0, pbuf1,
                                                 pw1a, pw2a, pt0, pt1);
    kconvH<64, false><<<grid, 512, CONVH_SMEM>>>(pt0, pt1, nullptr, nullptr,
                                                 pw1b, pw2b, out, out + TENSOR_ELEMS);
}

// round 16
// speedup vs baseline: 1.0102x; 1.0102x over previous
#include <cuda_runtime.h>
#include <cuda_fp16.h>
#include <cstddef>
#include <cstdint>

#define HH 320
#define WW 320
#define CC 64
#define BB 2
#define HW (HH*WW)              // 102400
#define CHW ((size_t)CC*HW)     // 6553600
#define TENSOR_ELEMS (BB*CHW)   // 13107200
#define CPHW ((size_t)32*HW)    // pair-planes per batch image

// Scratch (static device arrays; no allocation allowed)
__device__ uint32_t g_Mth[2*CC*32];          // fp16x2 Mt pairs: [dir][b][ap]
__device__ uint32_t g_bufh[2][BB*CPHW];      // attention buffers, fp16 pair-packed
__device__ uint32_t g_th[2][BB*CPHW];        // conv1 outputs, fp16 pair-packed
__device__ uint32_t g_uh[BB*CPHW];           // fp16 pair-packed u (written by kattn)
__device__ uint32_t g_dh[BB*CPHW];           // fp16 pair-packed d
// fp16 conv weights: [chunk][tap9][o64][kp8] half2 words
__device__ uint32_t g_wh1a[8*9*64*8];
__device__ uint32_t g_wh2a[8*9*64*8];
__device__ uint32_t g_wh1b[4*9*64*8];
__device__ uint32_t g_wh2b[4*9*64*8];

__device__ __forceinline__ void mma_f16(float4& d,
        uint32_t a0, uint32_t a1, uint32_t a2, uint32_t a3,
        uint32_t b0, uint32_t b1) {
    asm("mma.sync.aligned.m16n8k16.row.col.f32.f16.f16.f32 "
        "{%0,%1,%2,%3}, {%4,%5,%6,%7}, {%8,%9}, {%0,%1,%2,%3};"
        : "+f"(d.x), "+f"(d.y), "+f"(d.z), "+f"(d.w)
        : "r"(a0), "r"(a1), "r"(a2), "r"(a3), "r"(b0), "r"(b1));
}
__device__ __forceinline__ uint32_t prmt(uint32_t lo, uint32_t hi, uint32_t sel) {
    uint32_t r; asm("prmt.b32 %0, %1, %2, %3;" : "=r"(r) : "r"(lo), "r"(hi), "r"(sel));
    return r;
}
__device__ __forceinline__ void cp16(uint32_t saddr, const void* gaddr, uint32_t sz) {
    asm volatile("cp.async.cg.shared.global [%0], [%1], 16, %2;"
                 :: "r"(saddr), "l"(gaddr), "r"(sz));
}
__device__ __forceinline__ uint32_t h2u(__half2 h) { return *(uint32_t*)&h; }

// ---------------------------------------------------------------------------
// prep: fp16 conv weights (kp perm + sigma rows)
// ---------------------------------------------------------------------------
__device__ __forceinline__ void prepwh_one(const float* __restrict__ W,
                                           uint32_t* __restrict__ dst,
                                           int cin, int i) {
    int w      = i & 7;
    int o_st   = (i >> 3) & 63;
    int t      = (i >> 9) % 9;
    int chunk  = i / (9*64*8);
    int kpc = (w >> 1) + (w & 1)*4;
    int c0  = chunk*16 + 2*kpc;
    int r   = o_st & 15, tb = o_st & 48;
    int oc  = tb + (r & 7)*2 + (r >> 3);
    float w0 = W[((size_t)oc*cin + c0)*9 + t];
    float w1 = W[((size_t)oc*cin + c0 + 1)*9 + t];
    dst[i] = h2u(__floats2half2_rn(w0, w1));
}

#define WHA (8*9*64*8)   // 36864
#define WHB (4*9*64*8)   // 18432

__global__ void kprepwAll(const float* __restrict__ W1a, const float* __restrict__ W2a,
                          const float* __restrict__ W1b, const float* __restrict__ W2b) {
    int total = 2*WHA + 2*WHB;
    for (int i = blockIdx.x*256 + threadIdx.x; i < total; i += gridDim.x*256) {
        if (i < WHA)               prepwh_one(W1a, g_wh1a, 128, i);
        else if (i < 2*WHA)        prepwh_one(W2a, g_wh2a, 128, i - WHA);
        else if (i < 2*WHA + WHB)  prepwh_one(W1b, g_wh1b, 64,  i - 2*WHA);
        else                       prepwh_one(W2b, g_wh2b, 64,  i - 2*WHA - WHB);
    }
}

// ---------------------------------------------------------------------------
// Kernel 1: Mth[dir][b][ap] = half2( log2e*Mt[b][2ap], log2e*Mt[b][2ap+1] )
// ---------------------------------------------------------------------------
__global__ void kcomputeM2(const float* __restrict__ Wu1, const float* __restrict__ Wd2,
                           const float* __restrict__ Wd1, const float* __restrict__ Wu2) {
    __shared__ float sq[64*64];
    __shared__ float sk[64*64];
    int dir = blockIdx.x;
    const float* Wq = dir ? Wd1 : Wu1;
    const float* Wk = dir ? Wu2 : Wd2;
    int t = threadIdx.x;
    for (int i = t; i < 4096; i += 256) { sq[i] = Wq[i]; sk[i] = Wk[i]; }
    __syncthreads();
    const float LOG2E = 1.4426950408889634f;
    for (int i = t; i < 2048; i += 256) {
        int b  = i & 63;
        int ap = i >> 6;
        float s0 = 0.f, s1 = 0.f;
        #pragma unroll 16
        for (int c = 0; c < 64; c++) {
            s0 += sq[c*64 + 2*ap]     * sk[c*64 + b];
            s1 += sq[c*64 + 2*ap + 1] * sk[c*64 + b];
        }
        g_Mth[dir*2048 + b*32 + ap] = h2u(__floats2half2_rn(s0*LOG2E, s1*LOG2E));
    }
}

// ---------------------------------------------------------------------------
// Kernel 2: fp16 attention, register softmax (no max pass).
// One block per (b,h,dir): dir = blockIdx.y  (tail-wave reduction).
// ---------------------------------------------------------------------------
#define SP  328
#define SPH 172
#define SRP 40
#define ATTN_SMEM ((2*32*SP + 32*SPH + 32*SRP + 64*40 + 256)*4)

__global__ __launch_bounds__(512)
void kattn(const float* __restrict__ u, const float* __restrict__ d) {
    extern __shared__ uint32_t sm[];
    uint32_t* sup = sm;
    uint32_t* sdp = sm + 32*SP;
    uint32_t* sPh = sm + 2*32*SP;
    uint32_t* sRp = sPh + 32*SPH;
    float*    sO  = (float*)(sRp + 32*SRP);
    float*    sPsum = sO + 64*40;

    int tid  = threadIdx.x;
    int lane = tid & 31, warp = tid >> 5;    // 16 warps
    int gid  = lane >> 2, tid4 = lane & 3;
    int b = blockIdx.x / HH, h = blockIdx.x % HH;
    int dir = blockIdx.y;
    const float* ubase = u + (size_t)b*CHW + (size_t)h*WW;
    const float* dbase = d + (size_t)b*CHW + (size_t)h*WW;

    // stage pair-packed fp16 rows; persist one stream per dir (no dup stores)
    for (int i = tid; i < 32*80; i += 512) {
        int cp = i / 80, vq = (i % 80)*4;
        float4 ue = *(const float4*)(ubase + (size_t)(2*cp)*HW + vq);
        float4 uo = *(const float4*)(ubase + (size_t)(2*cp+1)*HW + vq);
        float4 de = *(const float4*)(dbase + (size_t)(2*cp)*HW + vq);
        float4 do_ = *(const float4*)(dbase + (size_t)(2*cp+1)*HW + vq);
        uint4 wu, wd;
        wu.x = h2u(__floats2half2_rn(ue.x, uo.x));
        wu.y = h2u(__floats2half2_rn(ue.y, uo.y));
        wu.z = h2u(__floats2half2_rn(ue.z, uo.z));
        wu.w = h2u(__floats2half2_rn(ue.w, uo.w));
        wd.x = h2u(__floats2half2_rn(de.x, do_.x));
        wd.y = h2u(__floats2half2_rn(de.y, do_.y));
        wd.z = h2u(__floats2half2_rn(de.z, do_.z));
        wd.w = h2u(__floats2half2_rn(de.w, do_.w));
        *(uint4*)&sup[cp*SP + vq] = wu;
        *(uint4*)&sdp[cp*SP + vq] = wd;
        size_t go = (size_t)b*CPHW + (size_t)cp*HW + (size_t)h*WW + vq;
        if (dir == 0) *(uint4*)&g_uh[go] = wu;
        else          *(uint4*)&g_dh[go] = wd;
    }
    __syncthreads();

    const uint32_t* sQ = dir ? sdp : sup;
    const uint32_t* sV = dir ? sup : sdp;
    uint32_t* outgh = g_bufh[dir] + (size_t)b*CPHW + (size_t)h*WW;

    const uint32_t* Mth = g_Mth + dir*2048;
    int bg = warp & 3, rq = warp >> 2;
    int r = bg*16 + gid;
    uint32_t am[4][4];
    #pragma unroll
    for (int kk = 0; kk < 4; kk++) {
        am[kk][0] = Mth[r*32 + kk*8 + tid4];
        am[kk][1] = Mth[(r+8)*32 + kk*8 + tid4];
        am[kk][2] = Mth[r*32 + kk*8 + tid4 + 4];
        am[kk][3] = Mth[(r+8)*32 + kk*8 + tid4 + 4];
    }

    for (int q0 = 0; q0 < WW; q0 += 32) {
        // ---- R[b][q]: 16b x 8q per warp, K=64 ----
        {
            float4 rc = make_float4(0.f,0.f,0.f,0.f);
            int qc = q0 + rq*8 + gid;
            #pragma unroll
            for (int kk = 0; kk < 4; kk++) {
                uint32_t b0 = sQ[(kk*8 + tid4)*SP + qc];
                uint32_t b1 = sQ[(kk*8 + tid4 + 4)*SP + qc];
                mma_f16(rc, am[kk][0], am[kk][1], am[kk][2], am[kk][3], b0, b1);
            }
            __half* rh = (__half*)sRp;
            int bp  = bg*8 + (gid >> 1);
            int par = gid & 1;
            int qq  = rq*8 + 2*tid4;
            rh[(bp*SRP + qq)*2 + par]         = __float2half_rn(rc.x);
            rh[(bp*SRP + qq + 1)*2 + par]     = __float2half_rn(rc.y);
            rh[((bp+4)*SRP + qq)*2 + par]     = __float2half_rn(rc.z);
            rh[((bp+4)*SRP + qq + 1)*2 + par] = __float2half_rn(rc.w);
        }
        __syncthreads();

        // ---- S[q][v] in registers + register softmax (no max pass) ----
        {
            int qg = warp >> 3, vg = warp & 7;
            float4 sc[5];
            #pragma unroll
            for (int nt = 0; nt < 5; nt++) sc[nt] = make_float4(0.f,0.f,0.f,0.f);
            #pragma unroll
            for (int kk = 0; kk < 4; kk++) {
                uint32_t a0 = sRp[(kk*8 + tid4)*SRP + qg*16 + gid];
                uint32_t a1 = sRp[(kk*8 + tid4)*SRP + qg*16 + gid + 8];
                uint32_t a2 = sRp[(kk*8 + tid4 + 4)*SRP + qg*16 + gid];
                uint32_t a3 = sRp[(kk*8 + tid4 + 4)*SRP + qg*16 + gid + 8];
                #pragma unroll
                for (int nt = 0; nt < 5; nt++) {
                    int vv = vg*40 + nt*8 + gid;
                    uint32_t b0 = sV[(kk*8 + tid4)*SP + vv];
                    uint32_t b1 = sV[(kk*8 + tid4 + 4)*SP + vv];
                    mma_f16(sc[nt], a0, a1, a2, a3, b0, b1);
                }
            }
            int row0 = qg*16 + gid;
            float s0 = 0.f, s1 = 0.f;
            #pragma unroll
            for (int nt = 0; nt < 5; nt++) {
                sc[nt].x = exp2f(sc[nt].x);
                sc[nt].y = exp2f(sc[nt].y);
                sc[nt].z = exp2f(sc[nt].z);
                sc[nt].w = exp2f(sc[nt].w);
                s0 += sc[nt].x + sc[nt].y;
                s1 += sc[nt].z + sc[nt].w;
            }
            s0 += __shfl_xor_sync(~0u, s0, 1);
            s0 += __shfl_xor_sync(~0u, s0, 2);
            s1 += __shfl_xor_sync(~0u, s1, 1);
            s1 += __shfl_xor_sync(~0u, s1, 2);
            if (tid4 == 0) {
                sPsum[row0*8 + vg]     = s0;
                sPsum[(row0+8)*8 + vg] = s1;
            }
            __syncthreads();
            float4 ga = *(const float4*)&sPsum[row0*8];
            float4 gb = *(const float4*)&sPsum[row0*8 + 4];
            float inv0 = 1.f / (ga.x + ga.y + ga.z + ga.w + gb.x + gb.y + gb.z + gb.w);
            ga = *(const float4*)&sPsum[(row0+8)*8];
            gb = *(const float4*)&sPsum[(row0+8)*8 + 4];
            float inv1 = 1.f / (ga.x + ga.y + ga.z + ga.w + gb.x + gb.y + gb.z + gb.w);
            #pragma unroll
            for (int nt = 0; nt < 5; nt++) {
                int vp = vg*20 + nt*4 + tid4;
                sPh[row0*SPH + vp]     = h2u(__floats2half2_rn(sc[nt].x*inv0, sc[nt].y*inv0));
                sPh[(row0+8)*SPH + vp] = h2u(__floats2half2_rn(sc[nt].z*inv1, sc[nt].w*inv1));
            }
        }
        __syncthreads();

        // ---- attend: warp = cg(4) x aqg(2) x kh(2); rows = adjacent ch pair ----
        {
            int cg = warp & 3, aqg = (warp >> 2) & 1, kh = warp >> 3;
            int gam = cg*8 + gid;
            int c0  = 2*gam;
            float4 oc[2];
            oc[0] = make_float4(0.f,0.f,0.f,0.f);
            oc[1] = make_float4(0.f,0.f,0.f,0.f);
            #pragma unroll 2
            for (int kk = 0; kk < 10; kk++) {
                int kb = kh*160 + kk*16;
                uint2 w0 = *(const uint2*)&sV[gam*SP + kb + 2*tid4];
                uint2 w1 = *(const uint2*)&sV[gam*SP + kb + 2*tid4 + 8];
                uint32_t a0 = prmt(w0.x, w0.y, 0x5410u);
                uint32_t a1 = prmt(w0.x, w0.y, 0x7632u);
                uint32_t a2 = prmt(w1.x, w1.y, 0x5410u);
                uint32_t a3 = prmt(w1.x, w1.y, 0x7632u);
                int vp = (kb >> 1) + tid4;
                #pragma unroll
                for (int nt = 0; nt < 2; nt++) {
                    int q = aqg*16 + nt*8 + gid;
                    uint32_t b0 = sPh[q*SPH + vp];
                    uint32_t b1 = sPh[q*SPH + vp + 4];
                    mma_f16(oc[nt], a0, a1, a2, a3, b0, b1);
                }
            }
            if (kh == 0) {
                #pragma unroll
                for (int nt = 0; nt < 2; nt++) {
                    int q = aqg*16 + nt*8 + 2*tid4;
                    *(float2*)&sO[c0*40 + q]     = make_float2(oc[nt].x, oc[nt].y);
                    *(float2*)&sO[(c0+1)*40 + q] = make_float2(oc[nt].z, oc[nt].w);
                }
            }
            __syncthreads();
            if (kh == 1) {
                #pragma unroll
                for (int nt = 0; nt < 2; nt++) {
                    int q = aqg*16 + nt*8 + 2*tid4;
                    float2 r0 = *(const float2*)&sO[c0*40 + q];
                    float2 r1 = *(const float2*)&sO[(c0+1)*40 + q];
                    uint2 wv;
                    wv.x = h2u(__floats2half2_rn(oc[nt].x + r0.x, oc[nt].z + r1.x));
                    wv.y = h2u(__floats2half2_rn(oc[nt].y + r0.y, oc[nt].w + r1.y));
                    *(uint2*)(outgh + (size_t)gam*HW + q0 + q) = wv;
                }
            }
            __syncthreads();
        }
    }
}

// ---------------------------------------------------------------------------
// Kernel 3: fp16 implicit-GEMM 3x3 conv (R14 version: pair-plane smem,
// stride 728, hoisted chunk-invariant staging indices).
// ---------------------------------------------------------------------------
#define PLH 728
#define SINH (8*PLH)                    // 5824
#define SWH  (9*64*8)                   // 4608
#define STH  (SINH + SWH)               // 10432
#define CONVH_SMEM (STH*2*4)            // 83456 bytes

template<int CIN, bool FUSE>
__global__ __launch_bounds__(512, 1)
void kconvH(const uint32_t* __restrict__ in1u, const uint32_t* __restrict__ in1d,
            const uint32_t* __restrict__ in2u, const uint32_t* __restrict__ in2d,
            const uint32_t* __restrict__ wpu,  const uint32_t* __restrict__ wpd,
            void* __restrict__ outu, void* __restrict__ outd) {
    extern __shared__ uint32_t csm[];

    int tid  = threadIdx.x;
    int lane = tid & 31, warp = tid >> 5;
    int x0 = blockIdx.x * 64;
    int y0 = blockIdx.y * 8;
    int z  = blockIdx.z;
    int b  = z & 1, st = z >> 1;

    const uint32_t* in1 = (st ? in1d : in1u) + (size_t)b*CPHW;
    const uint32_t* in2 = (CIN == 128) ? ((st ? in2d : in2u) + (size_t)b*CPHW) : nullptr;
    const uint32_t* wp  = st ? wpd  : wpu;
    void* outv          = st ? outd : outu;

    int warp_o = warp & 1;
    int warp_y = warp >> 1;         // 0..7
    int lq = lane >> 2;
    int lr = lane & 3;

    uint32_t s_base = (uint32_t)__cvta_generic_to_shared(csm);
    const int NCH = CIN/16;

    // ---- precompute chunk-invariant staging decomposition ----
    bool has3 = tid < 416;          // 1440 = 2*512 + 416
    int      pc_c[3];
    uint32_t pc_soff[3];
    int      pc_roff[3];
    uint32_t pc_ok[3];
    #pragma unroll
    for (int j = 0; j < 3; j++) {
        int i = tid + j*512;
        if (i < 1440) {
            int c   = i / 180;
            int rem = i % 180;
            int rr  = rem / 18;
            int q   = rem % 18;
            int gy = y0 + rr - 1;
            int gx = x0 - 4 + q*4;
            uint32_t ok = (gy >= 0 && gy < HH && gx >= 0 && gx < WW) ? 16u : 0u;
            pc_c[j]    = c;
            pc_soff[j] = (uint32_t)(c*PLH + rr*72 + q*4)*4;
            pc_roff[j] = ok ? gy*WW + gx : 0;
            pc_ok[j]   = ok;
        } else {
            pc_c[j] = 0; pc_soff[j] = 0; pc_roff[j] = 0; pc_ok[j] = 0;
        }
    }

    auto stage = [&](int cb, int bufi) {
        uint32_t sb = s_base + bufi*STH*4;
        #pragma unroll
        for (int j = 0; j < 3; j++) {
            if (j == 2 && !has3) break;
            int cpg = cb*8 + pc_c[j];
            const uint32_t* plane = (CIN == 128 && cpg >= 32)
                                  ? in2 + (size_t)(cpg - 32)*HW
                                  : in1 + (size_t)cpg*HW;
            cp16(sb + pc_soff[j], plane + pc_roff[j], pc_ok[j]);
        }
        const uint32_t* wsrc = wp + cb*SWH;
        #pragma unroll
        for (int j = 0; j < 3; j++) {
            int i = tid + j*512;
            if (i < SWH/4)
                cp16(sb + (SINH + i*4)*4, wsrc + i*4, 16);
        }
    };

    float4 acc[2][8];
    #pragma unroll
    for (int mt = 0; mt < 2; mt++)
        #pragma unroll
        for (int nt = 0; nt < 8; nt++) acc[mt][nt] = make_float4(0.f,0.f,0.f,0.f);

    stage(0, 0);
    asm volatile("cp.async.commit_group;" ::: "memory");

    for (int cb = 0; cb < NCH; cb++) {
        if (cb + 1 < NCH) {
            stage(cb + 1, (cb + 1) & 1);
            asm volatile("cp.async.commit_group;" ::: "memory");
            asm volatile("cp.async.wait_group 1;" ::: "memory");
        } else {
            asm volatile("cp.async.wait_group 0;" ::: "memory");
        }
        __syncthreads();

        const uint32_t* sin_ = csm + (cb & 1)*STH;
        const uint32_t* sw_  = sin_ + SINH;

        #pragma unroll
        for (int t = 0; t < 9; t++) {
            int ky = t/3, kx = t - ky*3;
            int row = warp_y + ky;
            int bbase = row*72 + kx + 3 + lq;
            uint2 ae0 = *(const uint2*)&sw_[(t*64 + warp_o*32 + lq)*8 + 2*lr];
            uint2 ao0 = *(const uint2*)&sw_[(t*64 + warp_o*32 + lq + 8)*8 + 2*lr];
            uint2 ae1 = *(const uint2*)&sw_[(t*64 + warp_o*32 + 16 + lq)*8 + 2*lr];
            uint2 ao1 = *(const uint2*)&sw_[(t*64 + warp_o*32 + 16 + lq + 8)*8 + 2*lr];
            int p0 = lr*PLH + bbase;
            int p1 = p0 + 4*PLH;
            #pragma unroll
            for (int nt = 0; nt < 8; nt++) {
                uint32_t b0 = sin_[p0 + 8*nt];
                uint32_t b1 = sin_[p1 + 8*nt];
                mma_f16(acc[0][nt], ae0.x, ao0.x, ae0.y, ao0.y, b0, b1);
                mma_f16(acc[1][nt], ae1.x, ao1.x, ae1.y, ao1.y, b0, b1);
            }
        }
        __syncthreads();
    }

    int y = y0 + warp_y;
    #pragma unroll
    for (int mt = 0; mt < 2; mt++) {
        int tb  = warp_o*32 + mt*16;
        int ch0 = tb + 2*lq;
        int cp  = (tb >> 1) + lq;
        #pragma unroll
        for (int nt = 0; nt < 8; nt++) {
            int x = x0 + nt*8 + 2*lr;
            float4 v = acc[mt][nt];
            if (FUSE) {
                uint32_t* outp = (uint32_t*)outv;
                uint2 wv;
                wv.x = h2u(__floats2half2_rn(fmaxf(v.x, 0.f), fmaxf(v.z, 0.f)));
                wv.y = h2u(__floats2half2_rn(fmaxf(v.y, 0.f), fmaxf(v.w, 0.f)));
                *(uint2*)(outp + (size_t)b*CPHW + (size_t)cp*HW + (size_t)y*WW + x) = wv;
            } else {
                float* outp = (float*)outv;
                size_t off = (size_t)b*CHW + (size_t)ch0*HW + (size_t)y*WW + x;
                *(float2*)(outp + off)      = make_float2(v.x, v.y);
                *(float2*)(outp + off + HW) = make_float2(v.z, v.w);
            }
        }
    }
}

// ---------------------------------------------------------------------------
extern "C" void kernel_launch(void* const* d_in, const int* in_sizes, int n_in,
                              void* d_out, int out_size) {
    const float* u   = (const float*)d_in[0];
    const float* d   = (const float*)d_in[1];
    const float* Wu1 = (const float*)d_in[2];
    const float* Wu2 = (const float*)d_in[3];
    const float* Wd1 = (const float*)d_in[4];
    const float* Wd2 = (const float*)d_in[5];
    const float* W1a = (const float*)d_in[6];
    const float* W1b = (const float*)d_in[7];
    const float* W2a = (const float*)d_in[8];
    const float* W2b = (const float*)d_in[9];
    float* out = (float*)d_out;

    cudaFuncSetAttribute(kattn, cudaFuncAttributeMaxDynamicSharedMemorySize, ATTN_SMEM);
    cudaFuncSetAttribute(kconvH<128, true>,  cudaFuncAttributeMaxDynamicSharedMemorySize, CONVH_SMEM);
    cudaFuncSetAttribute(kconvH<64, false>,  cudaFuncAttributeMaxDynamicSharedMemorySize, CONVH_SMEM);

    uint32_t *pbuf0, *pbuf1, *pt0, *pt1, *puh, *pdh;
    uint32_t *pw1a, *pw2a, *pw1b, *pw2b;
    cudaGetSymbolAddress((void**)&pbuf0, g_bufh);  pbuf1 = pbuf0 + BB*CPHW;
    cudaGetSymbolAddress((void**)&pt0,   g_th);    pt1   = pt0   + BB*CPHW;
    cudaGetSymbolAddress((void**)&puh,   g_uh);
    cudaGetSymbolAddress((void**)&pdh,   g_dh);
    cudaGetSymbolAddress((void**)&pw1a,  g_wh1a);
    cudaGetSymbolAddress((void**)&pw2a,  g_wh2a);
    cudaGetSymbolAddress((void**)&pw1b,  g_wh1b);
    cudaGetSymbolAddress((void**)&pw2b,  g_wh2b);

    kprepwAll<<<432, 256>>>(W1a, W2a, W1b, W2b);
    kcomputeM2<<<2, 256>>>(Wu1, Wd2, Wd1, Wu2);

    dim3 agrid(BB*HH, 2);
    kattn<<<agrid, 512, ATTN_SMEM>>>(u, d);

    dim3 grid(WW/64, HH/8, 4);
    kconvH<128, true><<<grid, 512, CONVH_SMEM>>>(puh, pdh, pbuf0, pbuf1,
                                                 pw1a, pw2a, pt0, pt1);
    kconvH<64, false><<<grid, 512, CONVH_SMEM>>>(pt0, pt1, nullptr, nullptr,
                                                 pw1b, pw2b, out, out + TENSOR_ELEMS);
}

// round 17
// speedup vs baseline: 1.0233x; 1.0129x over previous
#include <cuda_runtime.h>
#include <cuda_fp16.h>
#include <cstddef>
#include <cstdint>

#define HH 320
#define WW 320
#define CC 64
#define BB 2
#define HW (HH*WW)              // 102400
#define CHW ((size_t)CC*HW)     // 6553600
#define TENSOR_ELEMS (BB*CHW)   // 13107200
#define CPHW ((size_t)32*HW)    // pair-planes per batch image

// Scratch (static device arrays; no allocation allowed)
__device__ uint32_t g_Mth[2*CC*32];          // fp16x2 Mt pairs: [dir][b][ap]
__device__ uint32_t g_bufh[2][BB*CPHW];      // attention buffers, fp16 pair-packed
__device__ uint32_t g_th[2][BB*CPHW];        // conv1 outputs, fp16 pair-packed
__device__ uint32_t g_uh[BB*CPHW];           // fp16 pair-packed u (written by kattn)
__device__ uint32_t g_dh[BB*CPHW];           // fp16 pair-packed d
// fp16 conv weights: [chunk][tap9][o64][kp8] half2 words
__device__ uint32_t g_wh1a[8*9*64*8];
__device__ uint32_t g_wh2a[8*9*64*8];
__device__ uint32_t g_wh1b[4*9*64*8];
__device__ uint32_t g_wh2b[4*9*64*8];

__device__ __forceinline__ void mma_f16(float4& d,
        uint32_t a0, uint32_t a1, uint32_t a2, uint32_t a3,
        uint32_t b0, uint32_t b1) {
    asm("mma.sync.aligned.m16n8k16.row.col.f32.f16.f16.f32 "
        "{%0,%1,%2,%3}, {%4,%5,%6,%7}, {%8,%9}, {%0,%1,%2,%3};"
        : "+f"(d.x), "+f"(d.y), "+f"(d.z), "+f"(d.w)
        : "r"(a0), "r"(a1), "r"(a2), "r"(a3), "r"(b0), "r"(b1));
}
__device__ __forceinline__ uint32_t prmt(uint32_t lo, uint32_t hi, uint32_t sel) {
    uint32_t r; asm("prmt.b32 %0, %1, %2, %3;" : "=r"(r) : "r"(lo), "r"(hi), "r"(sel));
    return r;
}
__device__ __forceinline__ void cp16(uint32_t saddr, const void* gaddr, uint32_t sz) {
    asm volatile("cp.async.cg.shared.global [%0], [%1], 16, %2;"
                 :: "r"(saddr), "l"(gaddr), "r"(sz));
}
__device__ __forceinline__ uint32_t h2u(__half2 h) { return *(uint32_t*)&h; }

// ---------------------------------------------------------------------------
// prep: fp16 conv weights (kp perm + sigma rows)
// ---------------------------------------------------------------------------
__device__ __forceinline__ void prepwh_one(const float* __restrict__ W,
                                           uint32_t* __restrict__ dst,
                                           int cin, int i) {
    int w      = i & 7;
    int o_st   = (i >> 3) & 63;
    int t      = (i >> 9) % 9;
    int chunk  = i / (9*64*8);
    int kpc = (w >> 1) + (w & 1)*4;
    int c0  = chunk*16 + 2*kpc;
    int r   = o_st & 15, tb = o_st & 48;
    int oc  = tb + (r & 7)*2 + (r >> 3);
    float w0 = W[((size_t)oc*cin + c0)*9 + t];
    float w1 = W[((size_t)oc*cin + c0 + 1)*9 + t];
    dst[i] = h2u(__floats2half2_rn(w0, w1));
}

#define WHA (8*9*64*8)   // 36864
#define WHB (4*9*64*8)   // 18432

__global__ void kprepwAll(const float* __restrict__ W1a, const float* __restrict__ W2a,
                          const float* __restrict__ W1b, const float* __restrict__ W2b) {
    int total = 2*WHA + 2*WHB;
    for (int i = blockIdx.x*256 + threadIdx.x; i < total; i += gridDim.x*256) {
        if (i < WHA)               prepwh_one(W1a, g_wh1a, 128, i);
        else if (i < 2*WHA)        prepwh_one(W2a, g_wh2a, 128, i - WHA);
        else if (i < 2*WHA + WHB)  prepwh_one(W1b, g_wh1b, 64,  i - 2*WHA);
        else                       prepwh_one(W2b, g_wh2b, 64,  i - 2*WHA - WHB);
    }
}

// ---------------------------------------------------------------------------
// Kernel 1: Mth[dir][b][ap] = half2( log2e*Mt[b][2ap], log2e*Mt[b][2ap+1] )
// ---------------------------------------------------------------------------
__global__ void kcomputeM2(const float* __restrict__ Wu1, const float* __restrict__ Wd2,
                           const float* __restrict__ Wd1, const float* __restrict__ Wu2) {
    __shared__ float sq[64*64];
    __shared__ float sk[64*64];
    int dir = blockIdx.x;
    const float* Wq = dir ? Wd1 : Wu1;
    const float* Wk = dir ? Wu2 : Wd2;
    int t = threadIdx.x;
    for (int i = t; i < 4096; i += 256) { sq[i] = Wq[i]; sk[i] = Wk[i]; }
    __syncthreads();
    const float LOG2E = 1.4426950408889634f;
    for (int i = t; i < 2048; i += 256) {
        int b  = i & 63;
        int ap = i >> 6;
        float s0 = 0.f, s1 = 0.f;
        #pragma unroll 16
        for (int c = 0; c < 64; c++) {
            s0 += sq[c*64 + 2*ap]     * sk[c*64 + b];
            s1 += sq[c*64 + 2*ap + 1] * sk[c*64 + b];
        }
        g_Mth[dir*2048 + b*32 + ap] = h2u(__floats2half2_rn(s0*LOG2E, s1*LOG2E));
    }
}

// ---------------------------------------------------------------------------
// Kernel 2: fp16 attention, register softmax (no max pass).
// One block per (b,h,dir): dir = blockIdx.y.
// NEW: attend A fragments (from immutable sV) hoisted out of the q0 loop.
// ---------------------------------------------------------------------------
#define SP  328
#define SPH 172
#define SRP 40
#define ATTN_SMEM ((2*32*SP + 32*SPH + 32*SRP + 64*40 + 256)*4)

__global__ __launch_bounds__(512)
void kattn(const float* __restrict__ u, const float* __restrict__ d) {
    extern __shared__ uint32_t sm[];
    uint32_t* sup = sm;
    uint32_t* sdp = sm + 32*SP;
    uint32_t* sPh = sm + 2*32*SP;
    uint32_t* sRp = sPh + 32*SPH;
    float*    sO  = (float*)(sRp + 32*SRP);
    float*    sPsum = sO + 64*40;

    int tid  = threadIdx.x;
    int lane = tid & 31, warp = tid >> 5;    // 16 warps
    int gid  = lane >> 2, tid4 = lane & 3;
    int b = blockIdx.x / HH, h = blockIdx.x % HH;
    int dir = blockIdx.y;
    const float* ubase = u + (size_t)b*CHW + (size_t)h*WW;
    const float* dbase = d + (size_t)b*CHW + (size_t)h*WW;

    // stage pair-packed fp16 rows; persist one stream per dir (no dup stores)
    for (int i = tid; i < 32*80; i += 512) {
        int cp = i / 80, vq = (i % 80)*4;
        float4 ue = *(const float4*)(ubase + (size_t)(2*cp)*HW + vq);
        float4 uo = *(const float4*)(ubase + (size_t)(2*cp+1)*HW + vq);
        float4 de = *(const float4*)(dbase + (size_t)(2*cp)*HW + vq);
        float4 do_ = *(const float4*)(dbase + (size_t)(2*cp+1)*HW + vq);
        uint4 wu, wd;
        wu.x = h2u(__floats2half2_rn(ue.x, uo.x));
        wu.y = h2u(__floats2half2_rn(ue.y, uo.y));
        wu.z = h2u(__floats2half2_rn(ue.z, uo.z));
        wu.w = h2u(__floats2half2_rn(ue.w, uo.w));
        wd.x = h2u(__floats2half2_rn(de.x, do_.x));
        wd.y = h2u(__floats2half2_rn(de.y, do_.y));
        wd.z = h2u(__floats2half2_rn(de.z, do_.z));
        wd.w = h2u(__floats2half2_rn(de.w, do_.w));
        *(uint4*)&sup[cp*SP + vq] = wu;
        *(uint4*)&sdp[cp*SP + vq] = wd;
        size_t go = (size_t)b*CPHW + (size_t)cp*HW + (size_t)h*WW + vq;
        if (dir == 0) *(uint4*)&g_uh[go] = wu;
        else          *(uint4*)&g_dh[go] = wd;
    }
    __syncthreads();

    const uint32_t* sQ = dir ? sdp : sup;
    const uint32_t* sV = dir ? sup : sdp;
    uint32_t* outgh = g_bufh[dir] + (size_t)b*CPHW + (size_t)h*WW;

    // ---- hoisted R-GEMM A fragments (Mt) ----
    const uint32_t* Mth = g_Mth + dir*2048;
    int bg = warp & 3, rq = warp >> 2;
    int r = bg*16 + gid;
    uint32_t am[4][4];
    #pragma unroll
    for (int kk = 0; kk < 4; kk++) {
        am[kk][0] = Mth[r*32 + kk*8 + tid4];
        am[kk][1] = Mth[(r+8)*32 + kk*8 + tid4];
        am[kk][2] = Mth[r*32 + kk*8 + tid4 + 4];
        am[kk][3] = Mth[(r+8)*32 + kk*8 + tid4 + 4];
    }

    // ---- hoisted attend A fragments (V is immutable in smem) ----
    int acg = warp & 3, aaqg = (warp >> 2) & 1, akh = warp >> 3;
    int gam = acg*8 + gid;
    int ac0 = 2*gam;
    uint32_t aA[10][4];
    #pragma unroll
    for (int kk = 0; kk < 10; kk++) {
        int kb = akh*160 + kk*16;
        uint2 w0 = *(const uint2*)&sV[gam*SP + kb + 2*tid4];
        uint2 w1 = *(const uint2*)&sV[gam*SP + kb + 2*tid4 + 8];
        aA[kk][0] = prmt(w0.x, w0.y, 0x5410u);
        aA[kk][1] = prmt(w0.x, w0.y, 0x7632u);
        aA[kk][2] = prmt(w1.x, w1.y, 0x5410u);
        aA[kk][3] = prmt(w1.x, w1.y, 0x7632u);
    }
    int avp0 = akh*80 + tid4;   // P word base per kk: avp0 + kk*8

    for (int q0 = 0; q0 < WW; q0 += 32) {
        // ---- R[b][q]: 16b x 8q per warp, K=64 ----
        {
            float4 rc = make_float4(0.f,0.f,0.f,0.f);
            int qc = q0 + rq*8 + gid;
            #pragma unroll
            for (int kk = 0; kk < 4; kk++) {
                uint32_t b0 = sQ[(kk*8 + tid4)*SP + qc];
                uint32_t b1 = sQ[(kk*8 + tid4 + 4)*SP + qc];
                mma_f16(rc, am[kk][0], am[kk][1], am[kk][2], am[kk][3], b0, b1);
            }
            __half* rh = (__half*)sRp;
            int bp  = bg*8 + (gid >> 1);
            int par = gid & 1;
            int qq  = rq*8 + 2*tid4;
            rh[(bp*SRP + qq)*2 + par]         = __float2half_rn(rc.x);
            rh[(bp*SRP + qq + 1)*2 + par]     = __float2half_rn(rc.y);
            rh[((bp+4)*SRP + qq)*2 + par]     = __float2half_rn(rc.z);
            rh[((bp+4)*SRP + qq + 1)*2 + par] = __float2half_rn(rc.w);
        }
        __syncthreads();

        // ---- S[q][v] in registers + register softmax (no max pass) ----
        {
            int qg = warp >> 3, vg = warp & 7;
            float4 sc[5];
            #pragma unroll
            for (int nt = 0; nt < 5; nt++) sc[nt] = make_float4(0.f,0.f,0.f,0.f);
            #pragma unroll
            for (int kk = 0; kk < 4; kk++) {
                uint32_t a0 = sRp[(kk*8 + tid4)*SRP + qg*16 + gid];
                uint32_t a1 = sRp[(kk*8 + tid4)*SRP + qg*16 + gid + 8];
                uint32_t a2 = sRp[(kk*8 + tid4 + 4)*SRP + qg*16 + gid];
                uint32_t a3 = sRp[(kk*8 + tid4 + 4)*SRP + qg*16 + gid + 8];
                #pragma unroll
                for (int nt = 0; nt < 5; nt++) {
                    int vv = vg*40 + nt*8 + gid;
                    uint32_t b0 = sV[(kk*8 + tid4)*SP + vv];
                    uint32_t b1 = sV[(kk*8 + tid4 + 4)*SP + vv];
                    mma_f16(sc[nt], a0, a1, a2, a3, b0, b1);
                }
            }
            int row0 = qg*16 + gid;
            float s0 = 0.f, s1 = 0.f;
            #pragma unroll
            for (int nt = 0; nt < 5; nt++) {
                sc[nt].x = exp2f(sc[nt].x);
                sc[nt].y = exp2f(sc[nt].y);
                sc[nt].z = exp2f(sc[nt].z);
                sc[nt].w = exp2f(sc[nt].w);
                s0 += sc[nt].x + sc[nt].y;
                s1 += sc[nt].z + sc[nt].w;
            }
            s0 += __shfl_xor_sync(~0u, s0, 1);
            s0 += __shfl_xor_sync(~0u, s0, 2);
            s1 += __shfl_xor_sync(~0u, s1, 1);
            s1 += __shfl_xor_sync(~0u, s1, 2);
            if (tid4 == 0) {
                sPsum[row0*8 + vg]     = s0;
                sPsum[(row0+8)*8 + vg] = s1;
            }
            __syncthreads();
            float4 ga = *(const float4*)&sPsum[row0*8];
            float4 gb = *(const float4*)&sPsum[row0*8 + 4];
            float inv0 = 1.f / (ga.x + ga.y + ga.z + ga.w + gb.x + gb.y + gb.z + gb.w);
            ga = *(const float4*)&sPsum[(row0+8)*8];
            gb = *(const float4*)&sPsum[(row0+8)*8 + 4];
            float inv1 = 1.f / (ga.x + ga.y + ga.z + ga.w + gb.x + gb.y + gb.z + gb.w);
            #pragma unroll
            for (int nt = 0; nt < 5; nt++) {
                int vp = vg*20 + nt*4 + tid4;
                sPh[row0*SPH + vp]     = h2u(__floats2half2_rn(sc[nt].x*inv0, sc[nt].y*inv0));
                sPh[(row0+8)*SPH + vp] = h2u(__floats2half2_rn(sc[nt].z*inv1, sc[nt].w*inv1));
            }
        }
        __syncthreads();

        // ---- attend: hoisted A; warp = cg(4) x aqg(2) x kh(2) ----
        {
            float4 oc[2];
            oc[0] = make_float4(0.f,0.f,0.f,0.f);
            oc[1] = make_float4(0.f,0.f,0.f,0.f);
            #pragma unroll
            for (int kk = 0; kk < 10; kk++) {
                int vp = avp0 + kk*8;
                #pragma unroll
                for (int nt = 0; nt < 2; nt++) {
                    int q = aaqg*16 + nt*8 + gid;
                    uint32_t b0 = sPh[q*SPH + vp];
                    uint32_t b1 = sPh[q*SPH + vp + 4];
                    mma_f16(oc[nt], aA[kk][0], aA[kk][1], aA[kk][2], aA[kk][3], b0, b1);
                }
            }
            if (akh == 0) {
                #pragma unroll
                for (int nt = 0; nt < 2; nt++) {
                    int q = aaqg*16 + nt*8 + 2*tid4;
                    *(float2*)&sO[ac0*40 + q]     = make_float2(oc[nt].x, oc[nt].y);
                    *(float2*)&sO[(ac0+1)*40 + q] = make_float2(oc[nt].z, oc[nt].w);
                }
            }
            __syncthreads();
            if (akh == 1) {
                #pragma unroll
                for (int nt = 0; nt < 2; nt++) {
                    int q = aaqg*16 + nt*8 + 2*tid4;
                    float2 r0 = *(const float2*)&sO[ac0*40 + q];
                    float2 r1 = *(const float2*)&sO[(ac0+1)*40 + q];
                    uint2 wv;
                    wv.x = h2u(__floats2half2_rn(oc[nt].x + r0.x, oc[nt].z + r1.x));
                    wv.y = h2u(__floats2half2_rn(oc[nt].y + r0.y, oc[nt].w + r1.y));
                    *(uint2*)(outgh + (size_t)gam*HW + q0 + q) = wv;
                }
            }
            __syncthreads();
        }
    }
}

// ---------------------------------------------------------------------------
// Kernel 3: fp16 implicit-GEMM 3x3 conv (R14 version: pair-plane smem,
// stride 728, hoisted chunk-invariant staging indices).
// ---------------------------------------------------------------------------
#define PLH 728
#define SINH (8*PLH)                    // 5824
#define SWH  (9*64*8)                   // 4608
#define STH  (SINH + SWH)               // 10432
#define CONVH_SMEM (STH*2*4)            // 83456 bytes

template<int CIN, bool FUSE>
__global__ __launch_bounds__(512, 1)
void kconvH(const uint32_t* __restrict__ in1u, const uint32_t* __restrict__ in1d,
            const uint32_t* __restrict__ in2u, const uint32_t* __restrict__ in2d,
            const uint32_t* __restrict__ wpu,  const uint32_t* __restrict__ wpd,
            void* __restrict__ outu, void* __restrict__ outd) {
    extern __shared__ uint32_t csm[];

    int tid  = threadIdx.x;
    int lane = tid & 31, warp = tid >> 5;
    int x0 = blockIdx.x * 64;
    int y0 = blockIdx.y * 8;
    int z  = blockIdx.z;
    int b  = z & 1, st = z >> 1;

    const uint32_t* in1 = (st ? in1d : in1u) + (size_t)b*CPHW;
    const uint32_t* in2 = (CIN == 128) ? ((st ? in2d : in2u) + (size_t)b*CPHW) : nullptr;
    const uint32_t* wp  = st ? wpd  : wpu;
    void* outv          = st ? outd : outu;

    int warp_o = warp & 1;
    int warp_y = warp >> 1;         // 0..7
    int lq = lane >> 2;
    int lr = lane & 3;

    uint32_t s_base = (uint32_t)__cvta_generic_to_shared(csm);
    const int NCH = CIN/16;

    // ---- precompute chunk-invariant staging decomposition ----
    bool has3 = tid < 416;          // 1440 = 2*512 + 416
    int      pc_c[3];
    uint32_t pc_soff[3];
    int      pc_roff[3];
    uint32_t pc_ok[3];
    #pragma unroll
    for (int j = 0; j < 3; j++) {
        int i = tid + j*512;
        if (i < 1440) {
            int c   = i / 180;
            int rem = i % 180;
            int rr  = rem / 18;
            int q   = rem % 18;
            int gy = y0 + rr - 1;
            int gx = x0 - 4 + q*4;
            uint32_t ok = (gy >= 0 && gy < HH && gx >= 0 && gx < WW) ? 16u : 0u;
            pc_c[j]    = c;
            pc_soff[j] = (uint32_t)(c*PLH + rr*72 + q*4)*4;
            pc_roff[j] = ok ? gy*WW + gx : 0;
            pc_ok[j]   = ok;
        } else {
            pc_c[j] = 0; pc_soff[j] = 0; pc_roff[j] = 0; pc_ok[j] = 0;
        }
    }

    auto stage = [&](int cb, int bufi) {
        uint32_t sb = s_base + bufi*STH*4;
        #pragma unroll
        for (int j = 0; j < 3; j++) {
            if (j == 2 && !has3) break;
            int cpg = cb*8 + pc_c[j];
            const uint32_t* plane = (CIN == 128 && cpg >= 32)
                                  ? in2 + (size_t)(cpg - 32)*HW
                                  : in1 + (size_t)cpg*HW;
            cp16(sb + pc_soff[j], plane + pc_roff[j], pc_ok[j]);
        }
        const uint32_t* wsrc = wp + cb*SWH;
        #pragma unroll
        for (int j = 0; j < 3; j++) {
            int i = tid + j*512;
            if (i < SWH/4)
                cp16(sb + (SINH + i*4)*4, wsrc + i*4, 16);
        }
    };

    float4 acc[2][8];
    #pragma unroll
    for (int mt = 0; mt < 2; mt++)
        #pragma unroll
        for (int nt = 0; nt < 8; nt++) acc[mt][nt] = make_float4(0.f,0.f,0.f,0.f);

    stage(0, 0);
    asm volatile("cp.async.commit_group;" ::: "memory");

    for (int cb = 0; cb < NCH; cb++) {
        if (cb + 1 < NCH) {
            stage(cb + 1, (cb + 1) & 1);
            asm volatile("cp.async.commit_group;" ::: "memory");
            asm volatile("cp.async.wait_group 1;" ::: "memory");
        } else {
            asm volatile("cp.async.wait_group 0;" ::: "memory");
        }
        __syncthreads();

        const uint32_t* sin_ = csm + (cb & 1)*STH;
        const uint32_t* sw_  = sin_ + SINH;

        #pragma unroll
        for (int t = 0; t < 9; t++) {
            int ky = t/3, kx = t - ky*3;
            int row = warp_y + ky;
            int bbase = row*72 + kx + 3 + lq;
            uint2 ae0 = *(const uint2*)&sw_[(t*64 + warp_o*32 + lq)*8 + 2*lr];
            uint2 ao0 = *(const uint2*)&sw_[(t*64 + warp_o*32 + lq + 8)*8 + 2*lr];
            uint2 ae1 = *(const uint2*)&sw_[(t*64 + warp_o*32 + 16 + lq)*8 + 2*lr];
            uint2 ao1 = *(const uint2*)&sw_[(t*64 + warp_o*32 + 16 + lq + 8)*8 + 2*lr];
            int p0 = lr*PLH + bbase;
            int p1 = p0 + 4*PLH;
            #pragma unroll
            for (int nt = 0; nt < 8; nt++) {
                uint32_t b0 = sin_[p0 + 8*nt];
                uint32_t b1 = sin_[p1 + 8*nt];
                mma_f16(acc[0][nt], ae0.x, ao0.x, ae0.y, ao0.y, b0, b1);
                mma_f16(acc[1][nt], ae1.x, ao1.x, ae1.y, ao1.y, b0, b1);
            }
        }
        __syncthreads();
    }

    int y = y0 + warp_y;
    #pragma unroll
    for (int mt = 0; mt < 2; mt++) {
        int tb  = warp_o*32 + mt*16;
        int ch0 = tb + 2*lq;
        int cp  = (tb >> 1) + lq;
        #pragma unroll
        for (int nt = 0; nt < 8; nt++) {
            int x = x0 + nt*8 + 2*lr;
            float4 v = acc[mt][nt];
            if (FUSE) {
                uint32_t* outp = (uint32_t*)outv;
                uint2 wv;
                wv.x = h2u(__floats2half2_rn(fmaxf(v.x, 0.f), fmaxf(v.z, 0.f)));
                wv.y = h2u(__floats2half2_rn(fmaxf(v.y, 0.f), fmaxf(v.w, 0.f)));
                *(uint2*)(outp + (size_t)b*CPHW + (size_t)cp*HW + (size_t)y*WW + x) = wv;
            } else {
                float* outp = (float*)outv;
                size_t off = (size_t)b*CHW + (size_t)ch0*HW + (size_t)y*WW + x;
                *(float2*)(outp + off)      = make_float2(v.x, v.y);
                *(float2*)(outp + off + HW) = make_float2(v.z, v.w);
            }
        }
    }
}

// ---------------------------------------------------------------------------
extern "C" void kernel_launch(void* const* d_in, const int* in_sizes, int n_in,
                              void* d_out, int out_size) {
    const float* u   = (const float*)d_in[0];
    const float* d   = (const float*)d_in[1];
    const float* Wu1 = (const float*)d_in[2];
    const float* Wu2 = (const float*)d_in[3];
    const float* Wd1 = (const float*)d_in[4];
    const float* Wd2 = (const float*)d_in[5];
    const float* W1a = (const float*)d_in[6];
    const float* W1b = (const float*)d_in[7];
    const float* W2a = (const float*)d_in[8];
    const float* W2b = (const float*)d_in[9];
    float* out = (float*)d_out;

    cudaFuncSetAttribute(kattn, cudaFuncAttributeMaxDynamicSharedMemorySize, ATTN_SMEM);
    cudaFuncSetAttribute(kconvH<128, true>,  cudaFuncAttributeMaxDynamicSharedMemorySize, CONVH_SMEM);
    cudaFuncSetAttribute(kconvH<64, false>,  cudaFuncAttributeMaxDynamicSharedMemorySize, CONVH_SMEM);

    uint32_t *pbuf0, *pbuf1, *pt0, *pt1, *puh, *pdh;
    uint32_t *pw1a, *pw2a, *pw1b, *pw2b;
    cudaGetSymbolAddress((void**)&pbuf0, g_bufh);  pbuf1 = pbuf0 + BB*CPHW;
    cudaGetSymbolAddress((void**)&pt0,   g_th);    pt1   = pt0   + BB*CPHW;
    cudaGetSymbolAddress((void**)&puh,   g_uh);
    cudaGetSymbolAddress((void**)&pdh,   g_dh);
    cudaGetSymbolAddress((void**)&pw1a,  g_wh1a);
    cudaGetSymbolAddress((void**)&pw2a,  g_wh2a);
    cudaGetSymbolAddress((void**)&pw1b,  g_wh1b);
    cudaGetSymbolAddress((void**)&pw2b,  g_wh2b);

    kprepwAll<<<432, 256>>>(W1a, W2a, W1b, W2b);
    kcomputeM2<<<2, 256>>>(Wu1, Wd2, Wd1, Wu2);

    dim3 agrid(BB*HH, 2);
    kattn<<<agrid, 512, ATTN_SMEM>>>(u, d);

    dim3 grid(WW/64, HH/8, 4);
    kconvH<128, true><<<grid, 512, CONVH_SMEM>>>(puh, pdh, pbuf0, pbuf1,
                                                 pw1a, pw2a, pt0, pt1);
    kconvH<64, false><<<grid, 512, CONVH_SMEM>>>(pt0, pt1, nullptr, nullptr,
                                                 pw1b, pw2b, out, out + TENSOR_ELEMS);
}